// round 17
// baseline (speedup 1.0000x reference)
#include <cuda_runtime.h>
#include <cuda_fp16.h>
#include <cstdint>

// Problem constants (match reference_code)
#define IN_C    128
#define HID_C   256
#define OUT_C   128
#define N_NODES 50000
#define N_EDGES 600000
#define NB_SCAN 196              // ceil(N_NODES / 256)

// ---------------------------------------------------------------------------
// Scratch (no cudaMalloc allowed): device globals
// ---------------------------------------------------------------------------
__device__ int g_cnt_int  [N_NODES];     // zero at entry (re-zeroed by gather1)
__device__ int g_row_start[N_NODES + 1];
__device__ int g_cursor   [N_NODES];
__device__ int g_csr_src  [N_EDGES];

// fp16 feature pipeline
__device__ __half g_x  [(size_t)N_NODES * IN_C];
__device__ __half g_a1 [(size_t)N_NODES * IN_C];
__device__ __half g_h  [(size_t)N_NODES * HID_C];
__device__ __half g_y2l[(size_t)N_NODES * OUT_C];   // h @ W2l (fp16)

// Pre-truncated transposed weights (fp16):
//  wt1[n][k], n in [0,256), k in [0,256): k<128 -> W1l[k][n], else W1r[k-128][n]
//  wt2[n][k], n in [0,256), k in [0,256): n<128 -> W2l[k][n], else W2r[k][n-128]
__device__ __half g_wt1[HID_C * (2 * IN_C)];
__device__ __half g_wt2[(2 * OUT_C) * HID_C];

// ---------------------------------------------------------------------------
// Helpers
// ---------------------------------------------------------------------------
__device__ __forceinline__ uint32_t smem_to_u32(const void* p) {
    uint32_t a;
    asm("{ .reg .u64 t; cvta.to.shared.u64 t, %1; cvt.u32.u64 %0, t; }" : "=r"(a) : "l"(p));
    return a;
}

#define SMEM_SWIZZLE_128B(off) ((off) ^ (((off) >> 3) & 0x70))

__device__ __forceinline__ void ldsm_x4(uint32_t* r, uint32_t addr) {
    asm volatile("ldmatrix.sync.aligned.m8n8.x4.shared.b16 {%0,%1,%2,%3}, [%4];"
        : "=r"(r[0]), "=r"(r[1]), "=r"(r[2]), "=r"(r[3]) : "r"(addr));
}

__device__ __forceinline__ void mma_f16(float* c, const uint32_t* a, const uint32_t* b) {
    asm volatile("mma.sync.aligned.m16n8k16.row.col.f32.f16.f16.f32 "
        "{%0,%1,%2,%3}, {%4,%5,%6,%7}, {%8,%9}, {%0,%1,%2,%3};"
        : "+f"(c[0]), "+f"(c[1]), "+f"(c[2]), "+f"(c[3])
        : "r"(a[0]), "r"(a[1]), "r"(a[2]), "r"(a[3]), "r"(b[0]), "r"(b[1]));
}

__device__ __forceinline__ void cp_async16(uint32_t smem, const void* g, bool valid) {
    int sz = valid ? 16 : 0;
    asm volatile("cp.async.cg.shared.global [%0], [%1], 16, %2;"
        :: "r"(smem), "l"(g), "r"(sz) : "memory");
}
#define CP_COMMIT() asm volatile("cp.async.commit_group;" ::: "memory")
#define CP_WAIT(n)  asm volatile("cp.async.wait_group %0;" :: "n"(n) : "memory")

// ---------------------------------------------------------------------------
// Merged prologue: hist (edges) + feature fp32->fp16 + weight prep, one launch.
// ---------------------------------------------------------------------------
#define CVT_N4   (N_NODES * IN_C / 4)
#define PREP_N   (2 * 65536)
#define PRO_TOT  (N_EDGES + CVT_N4 + PREP_N)

__global__ void prologue_kernel(const int* __restrict__ dst,
                                const float* __restrict__ x,
                                const float* __restrict__ W1l,
                                const float* __restrict__ W1r,
                                const float* __restrict__ W2l,
                                const float* __restrict__ W2r)
{
    int gi = blockIdx.x * blockDim.x + threadIdx.x;
    if (gi < N_EDGES) {
        atomicAdd(&g_cnt_int[dst[gi]], 1);
        return;
    }
    gi -= N_EDGES;
    if (gi < CVT_N4) {
        float4 v = *(const float4*)(x + gi * 4);
        __half2* p = (__half2*)(g_x + (size_t)gi * 4);
        p[0] = __halves2half2(__float2half_rn(v.x), __float2half_rn(v.y));
        p[1] = __halves2half2(__float2half_rn(v.z), __float2half_rn(v.w));
        return;
    }
    gi -= CVT_N4;
    if (gi >= PREP_N) return;
    const int T1 = HID_C * 256;        // 65536
    if (gi < T1) {
        int n = gi / 256;
        int k = gi % 256;
        float v = (k < 128) ? W1l[(size_t)k * HID_C + n]
                            : W1r[(size_t)(k - 128) * HID_C + n];
        g_wt1[gi] = __float2half_rn(v);
    } else {
        int idx = gi - T1;
        int n = idx / HID_C;
        int k = idx % HID_C;
        float v = (n < 128) ? W2l[(size_t)k * OUT_C + n]
                            : W2r[(size_t)k * OUT_C + (n - 128)];
        g_wt2[idx] = __float2half_rn(v);
    }
}

// ---------------------------------------------------------------------------
// Single-launch CSR scan: each block computes its global prefix directly
// (grid-stride sum of counts before its chunk), then local-scans its chunk.
// Writes row_start + cursor. Does NOT zero cnt_int (gather1 does).
// ---------------------------------------------------------------------------
__global__ void scan_kernel()
{
    __shared__ int sdata[256];
    int tid = threadIdx.x;
    int base = blockIdx.x * 256;

    // global prefix of counts before this chunk
    int psum = 0;
    for (int i = tid; i < base; i += 256) psum += g_cnt_int[i];
    sdata[tid] = psum;
    __syncthreads();
    #pragma unroll
    for (int s = 128; s > 0; s >>= 1) {
        if (tid < s) sdata[tid] += sdata[tid + s];
        __syncthreads();
    }
    int prefix = sdata[0];
    __syncthreads();

    // local exclusive scan of this chunk
    int i = base + tid;
    int v = (i < N_NODES) ? g_cnt_int[i] : 0;
    sdata[tid] = v;
    __syncthreads();
    #pragma unroll
    for (int s = 1; s < 256; s <<= 1) {
        int t = (tid >= s) ? sdata[tid - s] : 0;
        __syncthreads();
        sdata[tid] += t;
        __syncthreads();
    }
    if (i < N_NODES) {
        int rs = prefix + sdata[tid] - v;
        g_row_start[i] = rs;
        g_cursor[i]    = rs;
    }
    if (blockIdx.x == NB_SCAN - 1 && tid == 255)
        g_row_start[N_NODES] = prefix + sdata[255];
}

__global__ void fill_kernel(const int* __restrict__ src, const int* __restrict__ dst)
{
    int e = blockIdx.x * blockDim.x + threadIdx.x;
    if (e < N_EDGES) {
        int pos = atomicAdd(&g_cursor[dst[e]], 1);
        g_csr_src[pos] = src[e];
    }
}

// ---------------------------------------------------------------------------
// Gather-aggregate (layer 1): fp16 in, fp32 accumulate, fp16 mean out.
// Also re-zeroes g_cnt_int[node] (restores the zero-at-entry invariant).
// ---------------------------------------------------------------------------
template<int C>
__global__ void gather_f16_kernel(const __half* __restrict__ f,
                                  __half* __restrict__ a)
{
    int node = blockIdx.x * (blockDim.x >> 5) + (threadIdx.x >> 5);
    if (node >= N_NODES) return;
    int lane = threadIdx.x & 31;
    int beg = g_row_start[node];
    int end = g_row_start[node + 1];
    if (lane == 0) g_cnt_int[node] = 0;

    constexpr int V = C / 128;
    float4 acc[V];
    #pragma unroll
    for (int v = 0; v < V; v++) acc[v] = make_float4(0.f, 0.f, 0.f, 0.f);

    for (int k = beg; k < end; k++) {
        int s = g_csr_src[k];
        const uint2* p = (const uint2*)(f + (size_t)s * C);
        #pragma unroll
        for (int v = 0; v < V; v++) {
            uint2 w = p[lane + 32 * v];
            float2 v0 = __half22float2(*(__half2*)&w.x);
            float2 v1 = __half22float2(*(__half2*)&w.y);
            acc[v].x += v0.x; acc[v].y += v0.y;
            acc[v].z += v1.x; acc[v].w += v1.y;
        }
    }
    float inv = 1.0f / (float)max(end - beg, 1);
    #pragma unroll
    for (int v = 0; v < V; v++) {
        uint2 w;
        *(__half2*)&w.x = __halves2half2(__float2half_rn(acc[v].x * inv),
                                         __float2half_rn(acc[v].y * inv));
        *(__half2*)&w.y = __halves2half2(__float2half_rn(acc[v].z * inv),
                                         __float2half_rn(acc[v].w * inv));
        ((uint2*)(a + (size_t)node * C))[lane + 32 * v] = w;
    }
}

// ---------------------------------------------------------------------------
// Layer-2 gather (commuted): out[node] += mean over in-edges of y2l[src]
// ---------------------------------------------------------------------------
__global__ void gather_acc_kernel(const __half* __restrict__ y2l,
                                  float* __restrict__ out)
{
    int node = blockIdx.x * (blockDim.x >> 5) + (threadIdx.x >> 5);
    if (node >= N_NODES) return;
    int lane = threadIdx.x & 31;
    int beg = g_row_start[node];
    int end = g_row_start[node + 1];

    float4 acc = make_float4(0.f, 0.f, 0.f, 0.f);
    for (int k = beg; k < end; k++) {
        int s = g_csr_src[k];
        uint2 w = ((const uint2*)(y2l + (size_t)s * OUT_C))[lane];
        float2 v0 = __half22float2(*(__half2*)&w.x);
        float2 v1 = __half22float2(*(__half2*)&w.y);
        acc.x += v0.x; acc.y += v0.y; acc.z += v1.x; acc.w += v1.y;
    }
    float inv = 1.0f / (float)max(end - beg, 1);
    float4* o = (float4*)(out + (size_t)node * OUT_C) + lane;
    float4 p = *o;
    p.x += acc.x * inv; p.y += acc.y * inv;
    p.z += acc.z * inv; p.w += acc.w * inv;
    *o = p;
}

// ---------------------------------------------------------------------------
// Pipelined warp-MMA GEMM, CTA tile 128(M) x 128(N), 8 warps, 3 stages.
// Warp tile 32(M) x 64(N): wm = wid & 3 (m band), wn = wid >> 2 (n half).
// Pure fp16 x fp16, fp32 accumulators: 1 MMA per (k16, n8) step.
// K_TOT in chunks of 64. HALVES=2: A=[A0|A1]; HALVES=1: A=A0.
// MODE 0 (layer1): h = relu(acc + bias) -> fp16.
// MODE 1 (layer2): cols<128 -> y2l fp16 (no bias); cols>=128 -> out fp32 +bias.
// SMEM per stage: A 16K | B 16K = 32KB; 3 stages = 96KB.
// ---------------------------------------------------------------------------
#define ST_A(s) (smem_raw + (s) * 32768)
#define ST_B(s) (smem_raw + (s) * 32768 + 16384)
#define MMA_SMEM_TOTAL 98304

template<int K_TOT, int HALVES, int N_TOT, int MODE>
__global__ __launch_bounds__(256)
void sage_mma_warp(const __half* __restrict__ A0,
                   const __half* __restrict__ A1,
                   const __half* __restrict__ Wt,
                   const float* __restrict__ bias,
                   __half* __restrict__ OutH,     // MODE1: y2l (fp16)
                   float* __restrict__ OutF2,     // MODE1: out (fp32)
                   __half* __restrict__ Cout,     // MODE0: h (fp16)
                   int M)
{
    extern __shared__ char smem_raw[];
    constexpr int CHUNKS = K_TOT / 64;
    constexpr int K_SRC  = K_TOT / HALVES;

    int tid  = threadIdx.x;
    int wid  = tid >> 5;
    int lane = tid & 31;
    int wm   = wid & 3;           // m band (x32)
    int wn   = wid >> 2;          // n half (x64)
    int m0 = blockIdx.x * 128;
    int n0 = blockIdx.y * 128;

    auto load_chunk = [&](int c, int s) {
        uint32_t sa = smem_to_u32(ST_A(s));
        uint32_t sb = smem_to_u32(ST_B(s));
        int row = tid >> 1;
        int j0  = (tid & 1) * 4;
        {
            bool first_src = (HALVES == 1) || (c < CHUNKS / 2);
            const __half* A = first_src ? A0 : A1;
            int k0 = (first_src ? c : c - CHUNKS / 2) * 64;
            int gm = m0 + row;
            bool valid = gm < M;
            const __half* p = A + (size_t)gm * K_SRC + k0;
            #pragma unroll
            for (int j = j0; j < j0 + 4; j++) {
                uint32_t off = SMEM_SWIZZLE_128B((uint32_t)(row * 128 + j * 16));
                cp_async16(sa + off, p + j * 8, valid);
            }
        }
        {
            int kg = c * 64;
            const __half* b = Wt + (size_t)(n0 + row) * K_TOT + kg;
            #pragma unroll
            for (int j = j0; j < j0 + 4; j++) {
                uint32_t off = SMEM_SWIZZLE_128B((uint32_t)(row * 128 + j * 16));
                cp_async16(sb + off, b + j * 8, true);
            }
        }
        CP_COMMIT();
    };

    float acc[2][8][4];
    #pragma unroll
    for (int mt = 0; mt < 2; mt++)
        #pragma unroll
        for (int nt = 0; nt < 8; nt++)
            #pragma unroll
            for (int q = 0; q < 4; q++) acc[mt][nt][q] = 0.f;

    load_chunk(0, 0);
    if (CHUNKS > 1) load_chunk(1, 1);

    for (int c = 0; c < CHUNKS; c++) {
        int s = c % 3;
        if (c + 2 < CHUNKS) {
            load_chunk(c + 2, (c + 2) % 3);
            CP_WAIT(2);
        } else if (c + 1 < CHUNKS) {
            CP_WAIT(1);
        } else {
            CP_WAIT(0);
        }
        __syncthreads();

        uint32_t sa = smem_to_u32(ST_A(s));
        uint32_t sb = smem_to_u32(ST_B(s));

        #pragma unroll
        for (int ks = 0; ks < 4; ks++) {
            uint32_t ah[2][4];
            #pragma unroll
            for (int mt = 0; mt < 2; mt++) {
                int r  = wm * 32 + mt * 16 + (lane & 7) + ((lane >> 3) & 1) * 8;
                int cb = ks * 32 + ((lane >> 4) & 1) * 16;
                uint32_t off = SMEM_SWIZZLE_128B((uint32_t)(r * 128 + cb));
                ldsm_x4(ah[mt], sa + off);
            }
            #pragma unroll
            for (int grp = 0; grp < 2; grp++) {
                uint32_t bh[2][4];
                #pragma unroll
                for (int q = 0; q < 2; q++) {
                    int nt0 = grp * 4 + q * 2;
                    int r  = wn * 64 + nt0 * 8 + (lane & 7) + ((lane >> 4) & 1) * 8;
                    int cb = ks * 32 + ((lane >> 3) & 1) * 16;
                    uint32_t off = SMEM_SWIZZLE_128B((uint32_t)(r * 128 + cb));
                    ldsm_x4(bh[q], sb + off);
                }
                #pragma unroll
                for (int mt = 0; mt < 2; mt++)
                    #pragma unroll
                    for (int q = 0; q < 2; q++)
                        #pragma unroll
                        for (int sub = 0; sub < 2; sub++) {
                            int nt = grp * 4 + q * 2 + sub;
                            mma_f16(acc[mt][nt], ah[mt], &bh[q][sub * 2]);
                        }
            }
        }
        __syncthreads();
    }

    // ---- epilogue ----
    int g = lane >> 2;
    int t = lane & 3;
    #pragma unroll
    for (int mt = 0; mt < 2; mt++) {
        int r0 = m0 + wm * 32 + mt * 16 + g;
        int r1 = r0 + 8;
        #pragma unroll
        for (int nt = 0; nt < 8; nt++) {
            int n = n0 + wn * 64 + nt * 8 + 2 * t;
            float* a = acc[mt][nt];
            if (MODE == 0) {
                float2 bb = *(const float2*)(bias + n);
                float c0 = fmaxf(a[0] + bb.x, 0.f);
                float c1 = fmaxf(a[1] + bb.y, 0.f);
                float c2 = fmaxf(a[2] + bb.x, 0.f);
                float c3 = fmaxf(a[3] + bb.y, 0.f);
                if (r0 < M) *(__half2*)(Cout + (size_t)r0 * N_TOT + n) =
                    __halves2half2(__float2half_rn(c0), __float2half_rn(c1));
                if (r1 < M) *(__half2*)(Cout + (size_t)r1 * N_TOT + n) =
                    __halves2half2(__float2half_rn(c2), __float2half_rn(c3));
            } else {
                if (n < 128) {
                    if (r0 < M) *(__half2*)(OutH + (size_t)r0 * 128 + n) =
                        __halves2half2(__float2half_rn(a[0]), __float2half_rn(a[1]));
                    if (r1 < M) *(__half2*)(OutH + (size_t)r1 * 128 + n) =
                        __halves2half2(__float2half_rn(a[2]), __float2half_rn(a[3]));
                } else {
                    int nn = n - 128;
                    float2 bb = *(const float2*)(bias + nn);
                    if (r0 < M) *(float2*)(OutF2 + (size_t)r0 * 128 + nn) =
                        make_float2(a[0] + bb.x, a[1] + bb.y);
                    if (r1 < M) *(float2*)(OutF2 + (size_t)r1 * 128 + nn) =
                        make_float2(a[2] + bb.x, a[3] + bb.y);
                }
            }
        }
    }
}

// ---------------------------------------------------------------------------
// Launch
// ---------------------------------------------------------------------------
extern "C" void kernel_launch(void* const* d_in, const int* in_sizes, int n_in,
                              void* d_out, int out_size)
{
    const float* x   = (const float*)d_in[0];
    const int*   ei  = (const int*)d_in[1];     // int32 (JAX x64 disabled)
    const float* W1l = (const float*)d_in[2];
    const float* b1  = (const float*)d_in[3];
    const float* W1r = (const float*)d_in[4];
    const float* W2l = (const float*)d_in[5];
    const float* b2  = (const float*)d_in[6];
    const float* W2r = (const float*)d_in[7];
    float*       out = (float*)d_out;

    const int* src = ei;
    const int* dst = ei + N_EDGES;

    __half *xh, *a1, *h, *wt1, *wt2, *y2l;
    cudaGetSymbolAddress((void**)&y2l, g_y2l);
    cudaGetSymbolAddress((void**)&xh,  g_x);
    cudaGetSymbolAddress((void**)&a1,  g_a1);
    cudaGetSymbolAddress((void**)&h,   g_h);
    cudaGetSymbolAddress((void**)&wt1, g_wt1);
    cudaGetSymbolAddress((void**)&wt2, g_wt2);

    auto gemm1 = sage_mma_warp<256, 2, 256, 0>;
    auto gemm2 = sage_mma_warp<256, 1, 256, 1>;
    cudaFuncSetAttribute(gemm1, cudaFuncAttributeMaxDynamicSharedMemorySize, MMA_SMEM_TOTAL);
    cudaFuncSetAttribute(gemm2, cudaFuncAttributeMaxDynamicSharedMemorySize, MMA_SMEM_TOTAL);

    int mgrid = (N_NODES + 127) / 128;

    // ---- prologue: hist + feature cvt + weight prep (one launch) ----
    prologue_kernel<<<(PRO_TOT + 255) / 256, 256>>>(dst, x, W1l, W1r, W2l, W2r);

    // ---- CSR scan (single launch) + fill ----
    scan_kernel<<<NB_SCAN, 256>>>();
    fill_kernel<<<(N_EDGES + 255) / 256, 256>>>(src, dst);

    // ---- layer 1: gather x -> a1 (also re-zeroes cnt), then GEMM -> h ----
    {
        int warps_per_block = 8;
        int grid = (N_NODES + warps_per_block - 1) / warps_per_block;
        gather_f16_kernel<IN_C><<<grid, warps_per_block * 32>>>(xh, a1);
    }
    {
        dim3 grid(mgrid, 2);
        gemm1<<<grid, 256, MMA_SMEM_TOTAL>>>(
            a1, xh, wt1, b1, nullptr, nullptr, h, N_NODES);
    }

    // ---- layer 2 (gather commuted): h @ [W2l|W2r] -> y2l (fp16), out(+b2) ----
    {
        dim3 grid(mgrid, 2);
        gemm2<<<grid, 256, MMA_SMEM_TOTAL>>>(
            h, nullptr, wt2, b2, y2l, out, nullptr, N_NODES);
    }
    // out += mean-gather(y2l)
    {
        int warps_per_block = 8;
        int grid = (N_NODES + warps_per_block - 1) / warps_per_block;
        gather_acc_kernel<<<grid, warps_per_block * 32>>>(y2l, out);
    }
}